// round 17
// baseline (speedup 1.0000x reference)
#include <cuda_runtime.h>
#include <cuda_fp16.h>
#include <math.h>
#include <stdint.h>

#define N_NODES 100000
#define N_EDGES 3200000
#define D_IN    512
#define D_HID   256
#define D_OUT   64
#define KORD    10

#define SCAN_CHUNK   1024
#define NSCAN_BLOCKS 98          // ceil(100000/1024)

#define SPMV_BLOCKS  592         // ~1 wave of 512-thread blocks
#define EDGE_BLOCKS  1184        // ~1 wave of 256-thread blocks

// ---------------- device scratch (no allocations allowed) ----------------
__device__ int     g_cnt[N_NODES];
__device__ int     g_pos[N_NODES];
__device__ int     g_start[N_NODES + 1];
__device__ float   g_dinv[N_NODES];
__device__ int     g_bsum[NSCAN_BLOCKS];
__device__ int     g_bflag[NSCAN_BLOCKS];
__device__ int2    g_edge[N_EDGES];                        // (col, w bits) CSR by row
__device__ __half  g_w1h[(size_t)D_HID * D_IN];            // W1^T fp16 [256][512]
__device__ __half  g_w2h[(size_t)D_OUT * D_HID];           // W2^T fp16 [64][256]
__device__ __half  g_h1h[(size_t)N_NODES * D_HID];         // MLP hidden fp16
__device__ float   g_h [(size_t)N_NODES * D_OUT];          // MLP output fp32
__device__ __half2 g_hh[(size_t)N_NODES * (D_OUT / 2)];    // MLP output fp16
__device__ __half2 g_q0[(size_t)N_NODES * (D_OUT / 2)];    // Horner intermediates (fp16)
__device__ __half2 g_q1[(size_t)N_NODES * (D_OUT / 2)];
__device__ float   g_coef[KORD + 1];                       // monomial coeffs of poly in A
__device__ int     g_deg;                                  // true polynomial degree

// binomial coefficients C(n,k), n<=10 (exact integers)
__constant__ int c_comb[11][11] = {
    {1,0,0,0,0,0,0,0,0,0,0},
    {1,1,0,0,0,0,0,0,0,0,0},
    {1,2,1,0,0,0,0,0,0,0,0},
    {1,3,3,1,0,0,0,0,0,0,0},
    {1,4,6,4,1,0,0,0,0,0,0},
    {1,5,10,10,5,1,0,0,0,0,0},
    {1,6,15,20,15,6,1,0,0,0,0},
    {1,7,21,35,35,21,7,1,0,0,0},
    {1,8,28,56,70,56,28,8,1,0,0},
    {1,9,36,84,126,126,84,36,9,1,0},
    {1,10,45,120,210,252,210,120,45,10,1}
};

// ---------------- fused prep: convW1 + convW2 + zero cnt + flags + coef/degree ----------------
__global__ void prep_k(const float* __restrict__ W1, const float* __restrict__ W2,
                       const float* __restrict__ temp) {
    int b = blockIdx.x, tid = threadIdx.x;
    if (b < 512) {                               // W1 [512][256] -> W1^T fp16
        int i = b * 256 + tid;
        int k = i >> 8, n = i & 255;
        g_w1h[(size_t)n * D_IN + k] = __float2half_rn(W1[i]);
    } else if (b < 576) {                        // W2 [256][64] -> W2^T fp16
        int i = (b - 512) * 256 + tid;
        int k = i >> 6, n = i & 63;
        g_w2h[(size_t)n * D_HID + k] = __float2half_rn(W2[i]);
    } else if (b < 967) {                        // zero degree counts
        int i = (b - 576) * 256 + tid;
        if (i < N_NODES) g_cnt[i] = 0;
    } else {                                     // scan flags + Bernstein->monomial coeffs
        if (tid < NSCAN_BLOCKS) g_bflag[tid] = 0;
        __shared__ double sa[121];
        __shared__ int sdeg;
        if (tid == 0) sdeg = 0;
        if (tid < 121) {
            int k = tid / 11, j = tid % 11;
            double th = (double)temp[k];
            if (th < 0.0) th = 0.0;              // relu
            double ck = th * (double)c_comb[10][k] / 1024.0;
            double s = 0.0;
            for (int i2 = 0; i2 <= k; i2++) {
                int l = j - i2;
                if (l >= 0 && l <= 10 - k) {
                    double t = (double)c_comb[k][i2] * (double)c_comb[10 - k][l];
                    s += (i2 & 1) ? -t : t;
                }
            }
            sa[tid] = ck * s;
        }
        __syncthreads();
        if (tid < 11) {
            double a = 0.0;
            for (int k = 0; k < 11; k++) a += sa[k * 11 + tid];
            g_coef[tid] = (float)a;
            if (a != 0.0) atomicMax(&sdeg, tid);  // exact-zero test (integer convs + /2^10)
        }
        __syncthreads();
        if (tid == 0) g_deg = sdeg;
    }
}

// ---------------- CSR build (skipped entirely when degree == 0) ----------------
// grid-stride over edge pairs
__global__ void hist_k(const int* __restrict__ row) {
    if (g_deg == 0) return;
    int stride = gridDim.x * blockDim.x;
    for (int t = blockIdx.x * blockDim.x + threadIdx.x; t < N_EDGES / 2; t += stride) {
        int2 r2 = *reinterpret_cast<const int2*>(&row[t * 2]);
        atomicAdd(&g_cnt[r2.x], 1);
        atomicAdd(&g_cnt[r2.y], 1);
    }
}

// single-kernel exclusive scan via decoupled lookback (98 blocks, all co-resident)
__global__ void scanL_k() {
    if (g_deg == 0) return;
    __shared__ int ws[8];
    __shared__ int s_goff;
    int b = blockIdx.x, tid = threadIdx.x;
    int lane = tid & 31, warp = tid >> 5;
    if (tid == 0) s_goff = 0;
    int base = b * SCAN_CHUNK + tid * 4;
    int v[4];
    int ts = 0;
#pragma unroll
    for (int q = 0; q < 4; q++) {
        int i = base + q;
        v[q] = (i < N_NODES) ? g_cnt[i] : 0;
        ts += v[q];
    }
    int incl = ts;
#pragma unroll
    for (int o = 1; o < 32; o <<= 1) {
        int t = __shfl_up_sync(0xFFFFFFFFu, incl, o);
        if (lane >= o) incl += t;
    }
    if (lane == 31) ws[warp] = incl;
    __syncthreads();
    if (warp == 0 && lane < 8) {
        int w = ws[lane];
#pragma unroll
        for (int o = 1; o < 8; o <<= 1) {
            int t = __shfl_up_sync(0xFFu, w, o);
            if (lane >= o) w += t;
        }
        ws[lane] = w;
    }
    __syncthreads();
    if (tid == 0) {
        g_bsum[b] = ws[7];
        __threadfence();
        atomicExch(&g_bflag[b], 1);
    }
    if (tid < b) {
        while (atomicAdd(&g_bflag[tid], 0) == 0) {}
        atomicAdd(&s_goff, atomicAdd(&g_bsum[tid], 0));
    }
    __syncthreads();
    int off = s_goff + ((warp > 0) ? ws[warp - 1] : 0) + (incl - ts);
#pragma unroll
    for (int q = 0; q < 4; q++) {
        int i = base + q;
        if (i < N_NODES) {
            g_start[i] = off;
            g_pos[i]   = off;
            g_dinv[i]  = (v[q] > 0) ? rsqrtf((float)v[q]) : 0.0f;
        }
        off += v[q];
    }
    if (b == 0 && tid == 0) g_start[N_NODES] = N_EDGES;
}

// grid-stride over edge pairs
__global__ void scatter_k(const int* __restrict__ row, const int* __restrict__ col) {
    if (g_deg == 0) return;
    int stride = gridDim.x * blockDim.x;
    for (int t = blockIdx.x * blockDim.x + threadIdx.x; t < N_EDGES / 2; t += stride) {
        int2 r2 = *reinterpret_cast<const int2*>(&row[t * 2]);
        int2 c2 = *reinterpret_cast<const int2*>(&col[t * 2]);
        int p0 = atomicAdd(&g_pos[r2.x], 1);
        g_edge[p0] = make_int2(c2.x, __float_as_int(g_dinv[r2.x] * g_dinv[c2.x]));
        int p1 = atomicAdd(&g_pos[r2.y], 1);
        g_edge[p1] = make_int2(c2.y, __float_as_int(g_dinv[r2.y] * g_dinv[c2.y]));
    }
}

// ---------------- fp16 tensor-core GEMM (mma.sync m16n8k16 + ldmatrix) ----------------
__device__ __forceinline__ void mma_f16(float* d, const uint32_t* a, const uint32_t* b) {
    asm volatile(
        "mma.sync.aligned.m16n8k16.row.col.f32.f16.f16.f32 "
        "{%0,%1,%2,%3}, {%4,%5,%6,%7}, {%8,%9}, {%0,%1,%2,%3};"
        : "+f"(d[0]), "+f"(d[1]), "+f"(d[2]), "+f"(d[3])
        : "r"(a[0]), "r"(a[1]), "r"(a[2]), "r"(a[3]), "r"(b[0]), "r"(b[1]));
}

__device__ __forceinline__ void ldsm_x4(uint32_t* r, uint32_t addr) {
    asm volatile("ldmatrix.sync.aligned.m8n8.x4.shared.b16 {%0,%1,%2,%3}, [%4];"
                 : "=r"(r[0]), "=r"(r[1]), "=r"(r[2]), "=r"(r[3]) : "r"(addr));
}

// A: [M,Kd] row-major (fp32 if AF32, converted inline; else fp16).
// Bt: [Nd,Kd] fp16 (pre-transposed). C = relu?(A@B + bias).
// WF: write fp32 C ; WH: write fp16 copy to Ch.
// Block: WM x WN warps (NTH threads), CTA tile BM x BN, warp tile (BM/WM) x (BN/WN).
template <int BM, int BN, int WM, int WN, bool AF32, bool RELU, bool WF, bool WH>
__launch_bounds__(WM * WN * 32)
__global__ void gemm_h_k(const void* __restrict__ Ain, const __half* __restrict__ Bt,
                         const float* __restrict__ bias, float* __restrict__ C,
                         __half2* __restrict__ Ch, int M, int Kd, int Nd) {
    constexpr int NTH = WM * WN * 32;
    constexpr int BK = 32;
    constexpr int APITCH = BK + 8;                 // 40 halves = 80 bytes
    constexpr int BPITCH = BK + 8;
    constexpr int WTM = BM / WM;
    constexpr int WTN = BN / WN;
    constexpr int MT = WTM / 16;
    constexpr int NT = WTN / 8;                    // must be even (paired ldmatrix.x4)
    static_assert(NT % 2 == 0, "NT even");
    constexpr int AV4 = (BM * BK) / (NTH * 4);
    constexpr int AVH = (BM * BK) / (NTH * 8);
    constexpr int BV  = (BN * BK) / (NTH * 8);

    __shared__ __align__(16) __half As[BM * APITCH];
    __shared__ __align__(16) __half Bs[BN * BPITCH];

    const float*  Af = (const float*)Ain;
    const __half* Ah = (const __half*)Ain;

    const int tid  = threadIdx.x;
    const int lane = tid & 31;
    const int w    = tid >> 5;
    const int wm   = w % WM;
    const int wn   = w / WM;
    const int m0   = blockIdx.y * BM;
    const int n0   = blockIdx.x * BN;

    float acc[MT][NT][4];
#pragma unroll
    for (int i = 0; i < MT; i++)
#pragma unroll
        for (int j = 0; j < NT; j++)
#pragma unroll
            for (int q = 0; q < 4; q++) acc[i][j][q] = 0.0f;

    const uint32_t asB = (uint32_t)__cvta_generic_to_shared(As);
    const uint32_t bsB = (uint32_t)__cvta_generic_to_shared(Bs);
    const uint32_t aBase = asB + (uint32_t)(((wm * WTM + (lane & 15)) * APITCH + (lane >> 4) * 8) * 2);
    const uint32_t bBase = bsB + (uint32_t)(((wn * WTN + (lane & 7) + ((lane & 16) ? 8 : 0)) * BPITCH
                                             + ((lane >> 3) & 1) * 8) * 2);

    float4 aSf[AF32 ? AV4 : 1];
    uint4  aSh[AF32 ? 1 : AVH];
    uint4  bS[BV];

    // prefetch tile 0
    if (AF32) {
#pragma unroll
        for (int i = 0; i < AV4; i++) {
            int idx = tid + i * NTH;
            int r = idx >> 3, c = (idx & 7) * 4;
            int gm = min(m0 + r, M - 1);
            aSf[i] = *reinterpret_cast<const float4*>(&Af[(size_t)gm * Kd + c]);
        }
    } else {
#pragma unroll
        for (int i = 0; i < AVH; i++) {
            int idx = tid + i * NTH;
            int r = idx >> 2, c = (idx & 3) * 8;
            int gm = min(m0 + r, M - 1);
            aSh[i] = *reinterpret_cast<const uint4*>(&Ah[(size_t)gm * Kd + c]);
        }
    }
#pragma unroll
    for (int i = 0; i < BV; i++) {
        int idx = tid + i * NTH;
        int n = idx >> 2, kg = (idx & 3) * 8;
        bS[i] = *reinterpret_cast<const uint4*>(&Bt[(size_t)(n0 + n) * Kd + kg]);
    }

    for (int kt = 0; kt < Kd; kt += BK) {
        // stage regs -> smem
        if (AF32) {
#pragma unroll
            for (int i = 0; i < AV4; i++) {
                int idx = tid + i * NTH;
                int r = idx >> 3, c = (idx & 7) * 4;
                __half2 lo = __floats2half2_rn(aSf[i].x, aSf[i].y);
                __half2 hi = __floats2half2_rn(aSf[i].z, aSf[i].w);
                *reinterpret_cast<uint2*>(&As[r * APITCH + c]) =
                    make_uint2(*(uint32_t*)&lo, *(uint32_t*)&hi);
            }
        } else {
#pragma unroll
            for (int i = 0; i < AVH; i++) {
                int idx = tid + i * NTH;
                int r = idx >> 2, c = (idx & 3) * 8;
                *reinterpret_cast<uint4*>(&As[r * APITCH + c]) = aSh[i];
            }
        }
#pragma unroll
        for (int i = 0; i < BV; i++) {
            int idx = tid + i * NTH;
            int n = idx >> 2, kg = (idx & 3) * 8;
            *reinterpret_cast<uint4*>(&Bs[n * BPITCH + kg]) = bS[i];
        }
        __syncthreads();

        // prefetch next tile
        if (kt + BK < Kd) {
            if (AF32) {
#pragma unroll
                for (int i = 0; i < AV4; i++) {
                    int idx = tid + i * NTH;
                    int r = idx >> 3, c = (idx & 7) * 4;
                    int gm = min(m0 + r, M - 1);
                    aSf[i] = *reinterpret_cast<const float4*>(&Af[(size_t)gm * Kd + kt + BK + c]);
                }
            } else {
#pragma unroll
                for (int i = 0; i < AVH; i++) {
                    int idx = tid + i * NTH;
                    int r = idx >> 2, c = (idx & 3) * 8;
                    int gm = min(m0 + r, M - 1);
                    aSh[i] = *reinterpret_cast<const uint4*>(&Ah[(size_t)gm * Kd + kt + BK + c]);
                }
            }
#pragma unroll
            for (int i = 0; i < BV; i++) {
                int idx = tid + i * NTH;
                int n = idx >> 2, kg = (idx & 3) * 8;
                bS[i] = *reinterpret_cast<const uint4*>(&Bt[(size_t)(n0 + n) * Kd + kt + BK + kg]);
            }
        }

        // compute: 2 chunks of k16, fragments via ldmatrix
#pragma unroll
        for (int ch = 0; ch < 2; ch++) {
            uint32_t afr[MT][4], bfr[NT][2];
#pragma unroll
            for (int mt = 0; mt < MT; mt++)
                ldsm_x4(afr[mt], aBase + mt * 16 * APITCH * 2 + ch * 32);
#pragma unroll
            for (int np = 0; np < NT / 2; np++) {
                uint32_t t4[4];
                ldsm_x4(t4, bBase + np * 16 * BPITCH * 2 + ch * 32);
                bfr[2 * np][0] = t4[0];
                bfr[2 * np][1] = t4[1];
                bfr[2 * np + 1][0] = t4[2];
                bfr[2 * np + 1][1] = t4[3];
            }
#pragma unroll
            for (int mt = 0; mt < MT; mt++)
#pragma unroll
                for (int nt = 0; nt < NT; nt++)
                    mma_f16(acc[mt][nt], afr[mt], bfr[nt]);
        }
        __syncthreads();
    }

    // epilogue: bias (+relu)
#pragma unroll
    for (int mt = 0; mt < MT; mt++) {
#pragma unroll
        for (int nt = 0; nt < NT; nt++) {
            int col = n0 + wn * WTN + nt * 8 + (lane & 3) * 2;
            float bx = bias[col], by = bias[col + 1];
            int r0 = m0 + wm * WTM + mt * 16 + (lane >> 2);
            float vx = acc[mt][nt][0] + bx;
            float vy = acc[mt][nt][1] + by;
            if (RELU) { vx = fmaxf(vx, 0.0f); vy = fmaxf(vy, 0.0f); }
            if (r0 < M) {
                if (WF) *reinterpret_cast<float2*>(&C[(size_t)r0 * Nd + col]) = make_float2(vx, vy);
                if (WH) Ch[((size_t)r0 * Nd + col) >> 1] = __floats2half2_rn(vx, vy);
            }
            int r1 = r0 + 8;
            vx = acc[mt][nt][2] + bx;
            vy = acc[mt][nt][3] + by;
            if (RELU) { vx = fmaxf(vx, 0.0f); vy = fmaxf(vy, 0.0f); }
            if (r1 < M) {
                if (WF) *reinterpret_cast<float2*>(&C[(size_t)r1 * Nd + col]) = make_float2(vx, vy);
                if (WH) Ch[((size_t)r1 * Nd + col) >> 1] = __floats2half2_rn(vx, vy);
            }
        }
    }
}

// ---------------- Horner SpMV (fp16 gather, fp32 accumulate) ----------------
__device__ __forceinline__ void spmv_body(const __half2* __restrict__ vin,
                                          const float* __restrict__ h,
                                          int jadd, float gm, int wid, int lane,
                                          float& accx, float& accy) {
    float aj = g_coef[jadd];
    float2 hv = reinterpret_cast<const float2*>(h)[(size_t)wid * 32 + lane];
    accx = aj * hv.x;
    accy = aj * hv.y;
    int idx = g_start[wid];
    int e   = g_start[wid + 1];
    for (; idx + 16 <= e; idx += 16) {
        int2 ed[16];
        __half2 gv[16];
#pragma unroll
        for (int q = 0; q < 16; q++) ed[q] = g_edge[idx + q];
#pragma unroll
        for (int q = 0; q < 16; q++) gv[q] = vin[(size_t)ed[q].x * 32 + lane];
#pragma unroll
        for (int q = 0; q < 16; q++) {
            float w = gm * __int_as_float(ed[q].y);
            float2 f = __half22float2(gv[q]);
            accx = fmaf(w, f.x, accx);
            accy = fmaf(w, f.y, accy);
        }
    }
    for (; idx + 4 <= e; idx += 4) {
        int2 ed[4];
        __half2 gv[4];
#pragma unroll
        for (int q = 0; q < 4; q++) ed[q] = g_edge[idx + q];
#pragma unroll
        for (int q = 0; q < 4; q++) gv[q] = vin[(size_t)ed[q].x * 32 + lane];
#pragma unroll
        for (int q = 0; q < 4; q++) {
            float w = gm * __int_as_float(ed[q].y);
            float2 f = __half22float2(gv[q]);
            accx = fmaf(w, f.x, accx);
            accy = fmaf(w, f.y, accy);
        }
    }
    for (; idx < e; ++idx) {
        int2 ed = g_edge[idx];
        float w = gm * __int_as_float(ed.y);
        float2 f = __half22float2(vin[(size_t)ed.x * 32 + lane]);
        accx = fmaf(w, f.x, accx);
        accy = fmaf(w, f.y, accy);
    }
}

// Adaptive-degree Horner pass (grid-stride):
//   jpass > d : no-op ; jpass == d : vout = a_d * h (flat copy) ; jpass < d : gather pass
__launch_bounds__(512)
__global__ void spmv_h_k(const __half2* __restrict__ vin, __half2* __restrict__ vout,
                         const __half2* __restrict__ hh, const float* __restrict__ h,
                         int jpass) {
    int d = g_deg;
    if (jpass > d) return;
    const int total  = N_NODES * 32;
    const int stride = gridDim.x * blockDim.x;
    int g0 = blockIdx.x * blockDim.x + threadIdx.x;
    if (jpass == d) {
        float a = g_coef[d];
        for (int gidx = g0; gidx < total; gidx += stride) {
            float2 f = __half22float2(hh[gidx]);
            vout[gidx] = __floats2half2_rn(a * f.x, a * f.y);
        }
        return;
    }
    int lane = threadIdx.x & 31;
    bool first = (jpass == KORD - 1);          // only reachable when d == KORD
    const __half2* vsrc = first ? hh : vin;
    float gm = first ? g_coef[KORD] : 1.0f;
    for (int gidx = g0; gidx < total; gidx += stride) {
        int wid = gidx >> 5;
        float accx, accy;
        spmv_body(vsrc, h, jpass, gm, wid, lane, accx, accy);
        vout[(size_t)wid * 32 + lane] = __floats2half2_rn(accx, accy);
    }
}

// final pass (j = 0) fused with log_softmax (grid-stride); no gather when d == 0
__launch_bounds__(512)
__global__ void spmv_lsm_k(const __half2* __restrict__ vin, float* __restrict__ out,
                           const float* __restrict__ h) {
    const int total  = N_NODES * 32;
    const int stride = gridDim.x * blockDim.x;
    int lane = threadIdx.x & 31;
    int d = g_deg;
    for (int gidx = blockIdx.x * blockDim.x + threadIdx.x; gidx < total; gidx += stride) {
        int wid = gidx >> 5;
        float vx, vy;
        if (d == 0) {
            float a0 = g_coef[0];
            float2 hv = reinterpret_cast<const float2*>(h)[(size_t)wid * 32 + lane];
            vx = a0 * hv.x;
            vy = a0 * hv.y;
        } else {
            spmv_body(vin, h, 0, 1.0f, wid, lane, vx, vy);
        }
        float m = fmaxf(vx, vy);
#pragma unroll
        for (int o = 16; o; o >>= 1) m = fmaxf(m, __shfl_xor_sync(0xFFFFFFFFu, m, o));
        float s = expf(vx - m) + expf(vy - m);
#pragma unroll
        for (int o = 16; o; o >>= 1) s += __shfl_xor_sync(0xFFFFFFFFu, s, o);
        float l = m + logf(s);
        reinterpret_cast<float2*>(out)[(size_t)wid * 32 + lane] = make_float2(vx - l, vy - l);
    }
}

// ---------------- launcher ----------------
extern "C" void kernel_launch(void* const* d_in, const int* in_sizes, int n_in,
                              void* d_out, int out_size) {
    const float* x    = (const float*)d_in[0];
    const int*   ei   = (const int*)  d_in[1];
    const float* W1   = (const float*)d_in[2];
    const float* b1   = (const float*)d_in[3];
    const float* W2   = (const float*)d_in[4];
    const float* b2   = (const float*)d_in[5];
    const float* temp = (const float*)d_in[6];
    float*       out  = (float*)d_out;
    const int* row = ei;
    const int* col = ei + N_EDGES;

    float *ph;
    __half *pw1h, *pw2h, *ph1h;
    __half2 *phh, *pq0, *pq1;
    cudaGetSymbolAddress((void**)&pw1h, g_w1h);
    cudaGetSymbolAddress((void**)&pw2h, g_w2h);
    cudaGetSymbolAddress((void**)&ph1h, g_h1h);
    cudaGetSymbolAddress((void**)&ph,   g_h);
    cudaGetSymbolAddress((void**)&phh,  g_hh);
    cudaGetSymbolAddress((void**)&pq0,  g_q0);
    cudaGetSymbolAddress((void**)&pq1,  g_q1);

    // 1: fused prep (weights fp16^T, coeffs + degree, cnt zero, scan flags)
    prep_k<<<968, 256>>>(W1, W2, temp);
    // 2-3: CSR histogram + single-kernel lookback scan (early-exit when deg==0)
    hist_k<<<EDGE_BLOCKS, 256>>>(row);
    scanL_k<<<NSCAN_BLOCKS, 256>>>();
    // 4: GEMM1 (64x64 CTA, 128 thr — occupancy-optimized; ncu target slot)
    {
        dim3 g1(D_HID / 64, (N_NODES + 63) / 64);
        gemm_h_k<64, 64, 2, 2, true, true, false, true>
            <<<g1, 128>>>(x, pw1h, b1, nullptr, (__half2*)ph1h, N_NODES, D_IN, D_HID);
    }
    // 5: CSR scatter
    scatter_k<<<EDGE_BLOCKS, 256>>>(row, col);
    // 6: GEMM2 (fp16 in, fp32 + fp16 out)
    {
        dim3 g2(D_OUT / 64, (N_NODES + 63) / 64);
        gemm_h_k<64, 64, 2, 2, false, false, true, true>
            <<<g2, 128>>>(ph1h, pw2h, b2, ph, phh, N_NODES, D_HID, D_OUT);
    }

    // Adaptive-degree Horner: passes j = K-1 .. 1, then fused lsm pass (j = 0)
    __half2* qcur = phh;
    __half2* qout = pq0;
    for (int j = KORD - 1; j >= 1; j--) {
        spmv_h_k<<<SPMV_BLOCKS, 512>>>(qcur, qout, phh, ph, j);
        qcur = qout;
        qout = (qout == pq0) ? pq1 : pq0;
    }
    spmv_lsm_k<<<SPMV_BLOCKS, 512>>>(qcur, out, ph);
}